// round 5
// baseline (speedup 1.0000x reference)
#include <cuda_runtime.h>
#include <math.h>

#define NMAX 100000
#define EMAX 1700000   // E + self loops

#define SCAN_BLK   256
#define SCAN_ITEMS 8
#define SCAN_TILE  (SCAN_BLK * SCAN_ITEMS)   // 2048
#define SCAN_NTILE ((NMAX + SCAN_TILE - 1) / SCAN_TILE)

// ---------------- device scratch (no allocations allowed) ----------------
__device__ int   g_is64;
__device__ int   g_deg[NMAX];
__device__ int   g_rowptr[NMAX + 1];
__device__ int   g_cursor[NMAX];
__device__ int   g_bsum[SCAN_NTILE + 1];
__device__ int   g_csrc[EMAX];
__device__ float g_h1[NMAX * 128];
__device__ float g_al1s[NMAX * 4];
__device__ float g_al1d[NMAX * 4];
__device__ float g_agg1[NMAX * 128];
__device__ float g_h2[NMAX * 64];
__device__ float g_al2s[NMAX * 4];
__device__ float g_al2d[NMAX * 4];
__device__ float g_agg2[NMAX * 64];
__device__ float g_h3[NMAX];

// ---------------- helpers ----------------
__device__ __forceinline__ int ld_src(const int* ei, int E, int i) {
    return g_is64 ? ei[2 * i] : ei[i];
}
__device__ __forceinline__ int ld_dst(const int* ei, int E, int i) {
    return g_is64 ? ei[2 * E + 2 * i] : ei[E + i];
}
__device__ __forceinline__ float wred_max(float v) {
#pragma unroll
    for (int o = 16; o; o >>= 1) v = fmaxf(v, __shfl_xor_sync(0xffffffffu, v, o));
    return v;
}
__device__ __forceinline__ float wred_sum(float v) {
#pragma unroll
    for (int o = 16; o; o >>= 1) v += __shfl_xor_sync(0xffffffffu, v, o);
    return v;
}
__device__ __forceinline__ int wred_sum_i(int v) {
#pragma unroll
    for (int o = 16; o; o >>= 1) v += __shfl_xor_sync(0xffffffffu, v, o);
    return v;
}
__device__ __forceinline__ float lrelu(float e) { return e > 0.f ? e : 0.2f * e; }

// ---------------- CSR build ----------------
__global__ void k_detect(const int* __restrict__ ei) {
    if (threadIdx.x == 0 && blockIdx.x == 0) {
        int is64 = 1;
        for (int i = 1; i < 256; i += 2)
            if (ei[i] != 0) { is64 = 0; break; }
        g_is64 = is64;
    }
}

__global__ void k_zero(int N) {
    int i = blockIdx.x * blockDim.x + threadIdx.x;
    if (i < N) g_deg[i] = 0;
}

__global__ void k_count(const int* __restrict__ ei, int E) {
    int i = blockIdx.x * blockDim.x + threadIdx.x;
    if (i < E) atomicAdd(&g_deg[ld_dst(ei, E, i)], 1);
}

// two-level scan: per-tile sums -> serial tiny scan -> per-tile write
__global__ void k_bsum(int N) {
    int b = blockIdx.x, t = threadIdx.x;
    int base = b * SCAN_TILE + t * SCAN_ITEMS;
    int s = 0;
#pragma unroll
    for (int k = 0; k < SCAN_ITEMS; k++) {
        int i = base + k;
        if (i < N) s += g_deg[i] + 1;   // +1 self loop
    }
    s = wred_sum_i(s);
    __shared__ int sw[SCAN_BLK / 32];
    if ((t & 31) == 0) sw[t >> 5] = s;
    __syncthreads();
    if (t == 0) {
        int tot = 0;
#pragma unroll
        for (int i = 0; i < SCAN_BLK / 32; i++) tot += sw[i];
        g_bsum[b] = tot;
    }
}

__global__ void k_bscan(int N) {
    if (threadIdx.x == 0) {
        int nb = (N + SCAN_TILE - 1) / SCAN_TILE;
        int run = 0;
        for (int i = 0; i < nb; i++) { int v = g_bsum[i]; g_bsum[i] = run; run += v; }
        g_rowptr[N] = run;
    }
}

__global__ void k_wptr(int N) {
    int b = blockIdx.x, t = threadIdx.x;
    int lane = t & 31, w = t >> 5;
    int base = b * SCAN_TILE + t * SCAN_ITEMS;
    int v[SCAN_ITEMS];
    int s = 0;
#pragma unroll
    for (int k = 0; k < SCAN_ITEMS; k++) {
        int i = base + k;
        v[k] = (i < N) ? g_deg[i] + 1 : 0;
        s += v[k];
    }
    int incl = s;
#pragma unroll
    for (int o = 1; o < 32; o <<= 1) {
        int nvl = __shfl_up_sync(0xffffffffu, incl, o);
        if (lane >= o) incl += nvl;
    }
    __shared__ int sw[SCAN_BLK / 32];
    if (lane == 31) sw[w] = incl;
    __syncthreads();
    int wbase = 0;
#pragma unroll
    for (int i = 0; i < SCAN_BLK / 32; i++) if (i < w) wbase += sw[i];
    int run = g_bsum[b] + wbase + (incl - s);
#pragma unroll
    for (int k = 0; k < SCAN_ITEMS; k++) {
        int i = base + k;
        if (i < N) {
            g_rowptr[i] = run;
            g_cursor[i] = run;
            run += v[k];
        }
    }
}

__global__ void k_scatter(const int* __restrict__ ei, int E) {
    int i = blockIdx.x * blockDim.x + threadIdx.x;
    if (i < E) {
        int d = ld_dst(ei, E, i);
        int pos = atomicAdd(&g_cursor[d], 1);
        g_csrc[pos] = ld_src(ei, E, i);
    }
}

__global__ void k_self(int N) {
    int i = blockIdx.x * blockDim.x + threadIdx.x;
    if (i < N) {
        int pos = atomicAdd(&g_cursor[i], 1);
        g_csrc[pos] = i;
    }
}

// ---------------- layer 1 transform: h1 = x @ W1; al1s/al1d ----------------
__global__ void k_l1(const float* __restrict__ x, const float* __restrict__ W1,
                     const float* __restrict__ as1, const float* __restrict__ ad1, int N) {
    __shared__ float sW[7 * 128];
    __shared__ float sas[128], sad[128];
    __shared__ float sx[7];
    int t = threadIdx.x;  // 128 threads
    for (int i = t; i < 7 * 128; i += 128) sW[i] = W1[i];
    sas[t] = as1[t];
    sad[t] = ad1[t];
    __syncthreads();
    int w = t >> 5, lane = t & 31;
    for (int n = blockIdx.x; n < N; n += gridDim.x) {
        if (t < 7) sx[t] = x[n * 7 + t];
        __syncthreads();
        float acc = 0.f;
#pragma unroll
        for (int i = 0; i < 7; i++) acc = fmaf(sx[i], sW[i * 128 + t], acc);
        g_h1[(size_t)n * 128 + t] = acc;
        float ps = wred_sum(acc * sas[t]);   // warp w == head w (32 ch/head)
        float pd = wred_sum(acc * sad[t]);
        if (lane == 0) { g_al1s[n * 4 + w] = ps; g_al1d[n * 4 + w] = pd; }
        __syncthreads();  // protect sx for next node
    }
}

// ---------------- layer 2 transform: t = elu(agg1+b1); h2 = t @ W2 ----------------
__global__ void k_l2(const float* __restrict__ W2, const float* __restrict__ b1,
                     const float* __restrict__ as2, const float* __restrict__ ad2, int N) {
    __shared__ float sW[128 * 64];  // 32 KB
    __shared__ float sas[64], sad[64], sb[128];
    __shared__ float st[128];
    __shared__ float sp[128];
    int t = threadIdx.x;  // 128 threads
    for (int i = t; i < 128 * 64; i += 128) sW[i] = W2[i];
    if (t < 64) { sas[t] = as2[t]; sad[t] = ad2[t]; }
    sb[t] = b1[t];
    __syncthreads();
    int c = t & 63, half = t >> 6;
    for (int n = blockIdx.x; n < N; n += gridDim.x) {
        float v = g_agg1[(size_t)n * 128 + t] + sb[t];
        st[t] = v > 0.f ? v : expm1f(v);
        __syncthreads();
        float acc = 0.f;
#pragma unroll 16
        for (int i = 0; i < 64; i++) {
            int ii = half * 64 + i;
            acc = fmaf(st[ii], sW[ii * 64 + c], acc);
        }
        sp[t] = acc;
        __syncthreads();
        if (t < 64) {
            float hv = sp[t] + sp[t + 64];
            g_h2[(size_t)n * 64 + t] = hv;
            float ps = hv * sas[t], pd = hv * sad[t];
#pragma unroll
            for (int o = 8; o; o >>= 1) {
                ps += __shfl_xor_sync(0xffffffffu, ps, o);
                pd += __shfl_xor_sync(0xffffffffu, pd, o);
            }
            if ((t & 15) == 0) {
                int h = t >> 4;  // 16 ch/head
                g_al2s[n * 4 + h] = ps;
                g_al2d[n * 4 + h] = pd;
            }
        }
        __syncthreads();  // st reused next node
    }
}

// ---------------- layer 3 transform: h3 = elu(agg2+b2) @ W3 ----------------
__global__ void k_l3(const float* __restrict__ W3, const float* __restrict__ b2, int N) {
    int gw = (blockIdx.x * blockDim.x + threadIdx.x) >> 5;
    int lane = threadIdx.x & 31;
    if (gw >= N) return;
    float acc = 0.f;
#pragma unroll
    for (int k = 0; k < 2; k++) {
        int i = lane + 32 * k;
        float v = g_agg2[(size_t)gw * 64 + i] + b2[i];
        v = v > 0.f ? v : expm1f(v);
        acc = fmaf(v, W3[i], acc);
    }
    acc = wred_sum(acc);
    if (lane == 0) g_h3[gw] = acc;
}

// ---------------- aggregation layer 1 (H=4, 32 ch/head, C=128) ----------------
__global__ void k_agg1(int N) {
    __shared__ float s_alpha[8][32][4];
    __shared__ int   s_src[8][32];
    int wslot = threadIdx.x >> 5;
    int lane = threadIdx.x & 31;
    int d = blockIdx.x * 8 + wslot;
    if (d >= N) return;
    int beg = g_rowptr[d], end = g_rowptr[d + 1];
    float4 ad = ((const float4*)g_al1d)[d];
    float m0 = -1e30f, m1 = -1e30f, m2 = -1e30f, m3 = -1e30f;
    for (int i = beg + lane; i < end; i += 32) {
        int s = g_csrc[i];
        float4 as = ((const float4*)g_al1s)[s];
        m0 = fmaxf(m0, lrelu(as.x + ad.x));
        m1 = fmaxf(m1, lrelu(as.y + ad.y));
        m2 = fmaxf(m2, lrelu(as.z + ad.z));
        m3 = fmaxf(m3, lrelu(as.w + ad.w));
    }
    m0 = wred_max(m0); m1 = wred_max(m1); m2 = wred_max(m2); m3 = wred_max(m3);
    float s0 = 0.f, s1 = 0.f, s2 = 0.f, s3 = 0.f;
    for (int i = beg + lane; i < end; i += 32) {
        int s = g_csrc[i];
        float4 as = ((const float4*)g_al1s)[s];
        s0 += __expf(lrelu(as.x + ad.x) - m0);
        s1 += __expf(lrelu(as.y + ad.y) - m1);
        s2 += __expf(lrelu(as.z + ad.z) - m2);
        s3 += __expf(lrelu(as.w + ad.w) - m3);
    }
    s0 = wred_sum(s0); s1 = wred_sum(s1); s2 = wred_sum(s2); s3 = wred_sum(s3);
    float i0 = 1.f / (s0 + 1e-16f), i1 = 1.f / (s1 + 1e-16f);
    float i2 = 1.f / (s2 + 1e-16f), i3 = 1.f / (s3 + 1e-16f);
    float4 acc = make_float4(0.f, 0.f, 0.f, 0.f);
    int hsel = lane >> 3;  // 4 contiguous channels per lane; head = (lane*4)/32
    for (int base = beg; base < end; base += 32) {
        int cnt = min(32, end - base);
        int i = base + lane;
        if (i < end) {
            int s = g_csrc[i];
            s_src[wslot][lane] = s;
            float4 as = ((const float4*)g_al1s)[s];
            s_alpha[wslot][lane][0] = __expf(lrelu(as.x + ad.x) - m0) * i0;
            s_alpha[wslot][lane][1] = __expf(lrelu(as.y + ad.y) - m1) * i1;
            s_alpha[wslot][lane][2] = __expf(lrelu(as.z + ad.z) - m2) * i2;
            s_alpha[wslot][lane][3] = __expf(lrelu(as.w + ad.w) - m3) * i3;
        }
        __syncwarp();
        for (int j = 0; j < cnt; j++) {
            int s = s_src[wslot][j];
            float a = s_alpha[wslot][j][hsel];
            float4 hv = ((const float4*)(g_h1 + (size_t)s * 128))[lane];
            acc.x = fmaf(hv.x, a, acc.x);
            acc.y = fmaf(hv.y, a, acc.y);
            acc.z = fmaf(hv.z, a, acc.z);
            acc.w = fmaf(hv.w, a, acc.w);
        }
        __syncwarp();
    }
    ((float4*)(g_agg1 + (size_t)d * 128))[lane] = acc;
}

// ---------------- aggregation layer 2 (H=4, 16 ch/head, C=64) ----------------
__global__ void k_agg2(int N) {
    __shared__ float s_alpha[8][32][4];
    __shared__ int   s_src[8][32];
    int wslot = threadIdx.x >> 5;
    int lane = threadIdx.x & 31;
    int d = blockIdx.x * 8 + wslot;
    if (d >= N) return;
    int beg = g_rowptr[d], end = g_rowptr[d + 1];
    float4 ad = ((const float4*)g_al2d)[d];
    float m0 = -1e30f, m1 = -1e30f, m2 = -1e30f, m3 = -1e30f;
    for (int i = beg + lane; i < end; i += 32) {
        int s = g_csrc[i];
        float4 as = ((const float4*)g_al2s)[s];
        m0 = fmaxf(m0, lrelu(as.x + ad.x));
        m1 = fmaxf(m1, lrelu(as.y + ad.y));
        m2 = fmaxf(m2, lrelu(as.z + ad.z));
        m3 = fmaxf(m3, lrelu(as.w + ad.w));
    }
    m0 = wred_max(m0); m1 = wred_max(m1); m2 = wred_max(m2); m3 = wred_max(m3);
    float s0 = 0.f, s1 = 0.f, s2 = 0.f, s3 = 0.f;
    for (int i = beg + lane; i < end; i += 32) {
        int s = g_csrc[i];
        float4 as = ((const float4*)g_al2s)[s];
        s0 += __expf(lrelu(as.x + ad.x) - m0);
        s1 += __expf(lrelu(as.y + ad.y) - m1);
        s2 += __expf(lrelu(as.z + ad.z) - m2);
        s3 += __expf(lrelu(as.w + ad.w) - m3);
    }
    s0 = wred_sum(s0); s1 = wred_sum(s1); s2 = wred_sum(s2); s3 = wred_sum(s3);
    float i0 = 1.f / (s0 + 1e-16f), i1 = 1.f / (s1 + 1e-16f);
    float i2 = 1.f / (s2 + 1e-16f), i3 = 1.f / (s3 + 1e-16f);
    float2 acc = make_float2(0.f, 0.f);
    int hsel = lane >> 3;  // 2 contiguous channels per lane; head = (lane*2)/16
    for (int base = beg; base < end; base += 32) {
        int cnt = min(32, end - base);
        int i = base + lane;
        if (i < end) {
            int s = g_csrc[i];
            s_src[wslot][lane] = s;
            float4 as = ((const float4*)g_al2s)[s];
            s_alpha[wslot][lane][0] = __expf(lrelu(as.x + ad.x) - m0) * i0;
            s_alpha[wslot][lane][1] = __expf(lrelu(as.y + ad.y) - m1) * i1;
            s_alpha[wslot][lane][2] = __expf(lrelu(as.z + ad.z) - m2) * i2;
            s_alpha[wslot][lane][3] = __expf(lrelu(as.w + ad.w) - m3) * i3;
        }
        __syncwarp();
        for (int j = 0; j < cnt; j++) {
            int s = s_src[wslot][j];
            float a = s_alpha[wslot][j][hsel];
            float2 hv = ((const float2*)(g_h2 + (size_t)s * 64))[lane];
            acc.x = fmaf(hv.x, a, acc.x);
            acc.y = fmaf(hv.y, a, acc.y);
        }
        __syncwarp();
    }
    ((float2*)(g_agg2 + (size_t)d * 64))[lane] = acc;
}

// ---------------- layer 3 aggregation + sigmoid output ----------------
__global__ void k_agg3(const float* __restrict__ as3, const float* __restrict__ ad3,
                       const float* __restrict__ b3, float* __restrict__ out, int N) {
    int gw = (blockIdx.x * blockDim.x + threadIdx.x) >> 5;
    int lane = threadIdx.x & 31;
    if (gw >= N) return;
    float a_s = as3[0], a_d = ad3[0];
    float hd = g_h3[gw] * a_d;
    int beg = g_rowptr[gw], end = g_rowptr[gw + 1];
    float m = -1e30f;
    for (int i = beg + lane; i < end; i += 32) {
        float e = lrelu(g_h3[g_csrc[i]] * a_s + hd);
        m = fmaxf(m, e);
    }
    m = wred_max(m);
    float se = 0.f, sv = 0.f;
    for (int i = beg + lane; i < end; i += 32) {
        float hs = g_h3[g_csrc[i]];
        float ex = __expf(lrelu(hs * a_s + hd) - m);
        se += ex;
        sv = fmaf(ex, hs, sv);
    }
    se = wred_sum(se);
    sv = wred_sum(sv);
    if (lane == 0) {
        float o = sv / (se + 1e-16f) + b3[0];
        out[gw] = 100.f / (1.f + expf(-o));
    }
}

// ---------------- launch ----------------
extern "C" void kernel_launch(void* const* d_in, const int* in_sizes, int n_in,
                              void* d_out, int out_size) {
    const float* x   = (const float*)d_in[0];
    const int*   ei  = (const int*)d_in[1];   // int32 or int64 (auto-detected)
    const float* W1  = (const float*)d_in[2];
    const float* as1 = (const float*)d_in[3];
    const float* ad1 = (const float*)d_in[4];
    const float* b1  = (const float*)d_in[5];
    const float* W2  = (const float*)d_in[6];
    const float* as2 = (const float*)d_in[7];
    const float* ad2 = (const float*)d_in[8];
    const float* b2  = (const float*)d_in[9];
    const float* W3  = (const float*)d_in[10];
    const float* as3 = (const float*)d_in[11];
    const float* ad3 = (const float*)d_in[12];
    const float* b3  = (const float*)d_in[13];
    int N = in_sizes[0] / 7;
    int E = in_sizes[1] / 2;
    float* out = (float*)d_out;

    int ntile = (N + SCAN_TILE - 1) / SCAN_TILE;

    k_detect<<<1, 32>>>(ei);
    k_zero<<<(N + 255) / 256, 256>>>(N);
    k_count<<<(E + 255) / 256, 256>>>(ei, E);
    k_bsum<<<ntile, SCAN_BLK>>>(N);
    k_bscan<<<1, 32>>>(N);
    k_wptr<<<ntile, SCAN_BLK>>>(N);
    k_scatter<<<(E + 255) / 256, 256>>>(ei, E);
    k_self<<<(N + 255) / 256, 256>>>(N);

    k_l1<<<2048, 128>>>(x, W1, as1, ad1, N);
    k_agg1<<<(N + 7) / 8, 256>>>(N);
    k_l2<<<2048, 128>>>(W2, b1, as2, ad2, N);
    k_agg2<<<(N + 7) / 8, 256>>>(N);
    k_l3<<<(N * 32 + 255) / 256, 256>>>(W3, b2, N);
    k_agg3<<<(N + 7) / 8, 256>>>(as3, ad3, b3, out, N);
}

// round 6
// speedup vs baseline: 1.1212x; 1.1212x over previous
#include <cuda_runtime.h>
#include <math.h>

#define NMAX 100000
#define EMAX 1700000   // E + self loops

#define SCAN_BLK   256
#define SCAN_ITEMS 8
#define SCAN_TILE  (SCAN_BLK * SCAN_ITEMS)   // 2048
#define SCAN_NTILE ((NMAX + SCAN_TILE - 1) / SCAN_TILE)

// ---------------- device scratch (no allocations allowed) ----------------
__device__ int   g_is64;
__device__ int   g_deg[NMAX];
__device__ int   g_rowptr[NMAX + 1];
__device__ int   g_cursor[NMAX];
__device__ int   g_bsum[SCAN_NTILE + 1];
__device__ int   g_csrc[EMAX];
__device__ float g_h1[NMAX * 128];
__device__ float g_al1s[NMAX * 4];
__device__ float g_al1d[NMAX * 4];
__device__ float g_agg1[NMAX * 128];
__device__ float g_h2[NMAX * 64];
__device__ float g_al2s[NMAX * 4];
__device__ float g_al2d[NMAX * 4];
__device__ float g_agg2[NMAX * 64];
__device__ float g_h3[NMAX];

// ---------------- helpers ----------------
__device__ __forceinline__ int ld_src(const int* ei, int E, int i) {
    return g_is64 ? ei[2 * i] : ei[i];
}
__device__ __forceinline__ int ld_dst(const int* ei, int E, int i) {
    return g_is64 ? ei[2 * E + 2 * i] : ei[E + i];
}
__device__ __forceinline__ float wred_max(float v) {
#pragma unroll
    for (int o = 16; o; o >>= 1) v = fmaxf(v, __shfl_xor_sync(0xffffffffu, v, o));
    return v;
}
__device__ __forceinline__ float wred_sum(float v) {
#pragma unroll
    for (int o = 16; o; o >>= 1) v += __shfl_xor_sync(0xffffffffu, v, o);
    return v;
}
__device__ __forceinline__ int wred_sum_i(int v) {
#pragma unroll
    for (int o = 16; o; o >>= 1) v += __shfl_xor_sync(0xffffffffu, v, o);
    return v;
}
__device__ __forceinline__ float lrelu(float e) { return e > 0.f ? e : 0.2f * e; }

// ---------------- CSR build ----------------
__global__ void k_detect(const int* __restrict__ ei) {
    if (threadIdx.x == 0 && blockIdx.x == 0) {
        int is64 = 1;
        for (int i = 1; i < 256; i += 2)
            if (ei[i] != 0) { is64 = 0; break; }
        g_is64 = is64;
    }
}

__global__ void k_zero(int N) {
    int i = blockIdx.x * blockDim.x + threadIdx.x;
    if (i < N) g_deg[i] = 0;
}

__global__ void k_count(const int* __restrict__ ei, int E) {
    int i = blockIdx.x * blockDim.x + threadIdx.x;
    if (i < E) atomicAdd(&g_deg[ld_dst(ei, E, i)], 1);
}

// two-level scan: per-tile sums -> serial tiny scan -> per-tile write
__global__ void k_bsum(int N) {
    int b = blockIdx.x, t = threadIdx.x;
    int base = b * SCAN_TILE + t * SCAN_ITEMS;
    int s = 0;
#pragma unroll
    for (int k = 0; k < SCAN_ITEMS; k++) {
        int i = base + k;
        if (i < N) s += g_deg[i] + 1;   // +1 self loop
    }
    s = wred_sum_i(s);
    __shared__ int sw[SCAN_BLK / 32];
    if ((t & 31) == 0) sw[t >> 5] = s;
    __syncthreads();
    if (t == 0) {
        int tot = 0;
#pragma unroll
        for (int i = 0; i < SCAN_BLK / 32; i++) tot += sw[i];
        g_bsum[b] = tot;
    }
}

__global__ void k_bscan(int N) {
    if (threadIdx.x == 0) {
        int nb = (N + SCAN_TILE - 1) / SCAN_TILE;
        int run = 0;
        for (int i = 0; i < nb; i++) { int v = g_bsum[i]; g_bsum[i] = run; run += v; }
        g_rowptr[N] = run;
    }
}

__global__ void k_wptr(int N) {
    int b = blockIdx.x, t = threadIdx.x;
    int lane = t & 31, w = t >> 5;
    int base = b * SCAN_TILE + t * SCAN_ITEMS;
    int v[SCAN_ITEMS];
    int s = 0;
#pragma unroll
    for (int k = 0; k < SCAN_ITEMS; k++) {
        int i = base + k;
        v[k] = (i < N) ? g_deg[i] + 1 : 0;
        s += v[k];
    }
    int incl = s;
#pragma unroll
    for (int o = 1; o < 32; o <<= 1) {
        int nvl = __shfl_up_sync(0xffffffffu, incl, o);
        if (lane >= o) incl += nvl;
    }
    __shared__ int sw[SCAN_BLK / 32];
    if (lane == 31) sw[w] = incl;
    __syncthreads();
    int wbase = 0;
#pragma unroll
    for (int i = 0; i < SCAN_BLK / 32; i++) if (i < w) wbase += sw[i];
    int run = g_bsum[b] + wbase + (incl - s);
#pragma unroll
    for (int k = 0; k < SCAN_ITEMS; k++) {
        int i = base + k;
        if (i < N) {
            g_rowptr[i] = run;
            g_cursor[i] = run;
            run += v[k];
        }
    }
}

__global__ void k_scatter(const int* __restrict__ ei, int E) {
    int i = blockIdx.x * blockDim.x + threadIdx.x;
    if (i < E) {
        int d = ld_dst(ei, E, i);
        int pos = atomicAdd(&g_cursor[d], 1);
        g_csrc[pos] = ld_src(ei, E, i);
    }
}

__global__ void k_self(int N) {
    int i = blockIdx.x * blockDim.x + threadIdx.x;
    if (i < N) {
        int pos = atomicAdd(&g_cursor[i], 1);
        g_csrc[pos] = i;
    }
}

// ---------------- layer 1 transform: warp per node, no barriers ----------------
__global__ void k_l1(const float* __restrict__ x, const float* __restrict__ W1,
                     const float* __restrict__ as1, const float* __restrict__ ad1, int N) {
    __shared__ float sW[7 * 128];
    __shared__ float sas[128], sad[128];
    int t = threadIdx.x;  // 256 threads
    for (int i = t; i < 7 * 128; i += 256) sW[i] = W1[i];
    if (t < 128) { sas[t] = as1[t]; sad[t] = ad1[t]; }
    __syncthreads();
    int lane = t & 31;
    int n = (blockIdx.x * blockDim.x + t) >> 5;
    if (n >= N) return;
    float xv = (lane < 7) ? x[n * 7 + lane] : 0.f;
    float x0 = __shfl_sync(0xffffffffu, xv, 0);
    float x1 = __shfl_sync(0xffffffffu, xv, 1);
    float x2 = __shfl_sync(0xffffffffu, xv, 2);
    float x3 = __shfl_sync(0xffffffffu, xv, 3);
    float x4 = __shfl_sync(0xffffffffu, xv, 4);
    float x5 = __shfl_sync(0xffffffffu, xv, 5);
    float x6 = __shfl_sync(0xffffffffu, xv, 6);
#pragma unroll
    for (int k = 0; k < 4; k++) {   // head k, channels k*32+lane
        int c = k * 32 + lane;
        float acc = x0 * sW[c];
        acc = fmaf(x1, sW[128 + c], acc);
        acc = fmaf(x2, sW[256 + c], acc);
        acc = fmaf(x3, sW[384 + c], acc);
        acc = fmaf(x4, sW[512 + c], acc);
        acc = fmaf(x5, sW[640 + c], acc);
        acc = fmaf(x6, sW[768 + c], acc);
        g_h1[(size_t)n * 128 + c] = acc;
        float ps = wred_sum(acc * sas[c]);
        float pd = wred_sum(acc * sad[c]);
        if (lane == 0) { g_al1s[n * 4 + k] = ps; g_al1d[n * 4 + k] = pd; }
    }
}

// ---------------- layer 2 transform: t = elu(agg1+b1); h2 = t @ W2 ----------------
__global__ void k_l2(const float* __restrict__ W2, const float* __restrict__ b1,
                     const float* __restrict__ as2, const float* __restrict__ ad2, int N) {
    __shared__ float sW[128 * 64];  // 32 KB
    __shared__ float sas[64], sad[64], sb[128];
    __shared__ float st[128];
    __shared__ float sp[128];
    int t = threadIdx.x;  // 128 threads
    for (int i = t; i < 128 * 64; i += 128) sW[i] = W2[i];
    if (t < 64) { sas[t] = as2[t]; sad[t] = ad2[t]; }
    sb[t] = b1[t];
    __syncthreads();
    int c = t & 63, half = t >> 6;
    for (int n = blockIdx.x; n < N; n += gridDim.x) {
        float v = g_agg1[(size_t)n * 128 + t] + sb[t];
        st[t] = v > 0.f ? v : expm1f(v);
        __syncthreads();
        float acc = 0.f;
#pragma unroll 16
        for (int i = 0; i < 64; i++) {
            int ii = half * 64 + i;
            acc = fmaf(st[ii], sW[ii * 64 + c], acc);
        }
        sp[t] = acc;
        __syncthreads();
        if (t < 64) {
            float hv = sp[t] + sp[t + 64];
            g_h2[(size_t)n * 64 + t] = hv;
            float ps = hv * sas[t], pd = hv * sad[t];
#pragma unroll
            for (int o = 8; o; o >>= 1) {
                ps += __shfl_xor_sync(0xffffffffu, ps, o);
                pd += __shfl_xor_sync(0xffffffffu, pd, o);
            }
            if ((t & 15) == 0) {
                int h = t >> 4;  // 16 ch/head
                g_al2s[n * 4 + h] = ps;
                g_al2d[n * 4 + h] = pd;
            }
        }
        __syncthreads();  // st reused next node
    }
}

// ---------------- layer 3 transform: h3 = elu(agg2+b2) @ W3 ----------------
__global__ void k_l3(const float* __restrict__ W3, const float* __restrict__ b2, int N) {
    int gw = (blockIdx.x * blockDim.x + threadIdx.x) >> 5;
    int lane = threadIdx.x & 31;
    if (gw >= N) return;
    float acc = 0.f;
#pragma unroll
    for (int k = 0; k < 2; k++) {
        int i = lane + 32 * k;
        float v = g_agg2[(size_t)gw * 64 + i] + b2[i];
        v = v > 0.f ? v : expm1f(v);
        acc = fmaf(v, W3[i], acc);
    }
    acc = wred_sum(acc);
    if (lane == 0) g_h3[gw] = acc;
}

// ---------------- aggregation layer 1 (H=4, 32 ch/head, C=128) ----------------
__global__ void k_agg1(int N) {
    __shared__ float s_alpha[8][32][4];
    __shared__ int   s_src[8][32];
    int wslot = threadIdx.x >> 5;
    int lane = threadIdx.x & 31;
    int d = blockIdx.x * 8 + wslot;
    if (d >= N) return;
    int beg = g_rowptr[d], end = g_rowptr[d + 1];
    int cnt = end - beg;
    float4 ad = ((const float4*)g_al1d)[d];
    float4 acc = make_float4(0.f, 0.f, 0.f, 0.f);
    int hsel = lane >> 3;  // 4 contiguous channels per lane
    float i0, i1, i2, i3;

    if (cnt <= 32) {
        // -------- single-chunk fast path: 1 pass over logits --------
        bool act = lane < cnt;
        int s = act ? g_csrc[beg + lane] : 0;
        float4 as = act ? ((const float4*)g_al1s)[s] : make_float4(0.f, 0.f, 0.f, 0.f);
        float e0 = act ? lrelu(as.x + ad.x) : -1e30f;
        float e1 = act ? lrelu(as.y + ad.y) : -1e30f;
        float e2 = act ? lrelu(as.z + ad.z) : -1e30f;
        float e3 = act ? lrelu(as.w + ad.w) : -1e30f;
        float m0 = wred_max(e0), m1 = wred_max(e1), m2 = wred_max(e2), m3 = wred_max(e3);
        float ex0 = act ? __expf(e0 - m0) : 0.f;
        float ex1 = act ? __expf(e1 - m1) : 0.f;
        float ex2 = act ? __expf(e2 - m2) : 0.f;
        float ex3 = act ? __expf(e3 - m3) : 0.f;
        i0 = 1.f / (wred_sum(ex0) + 1e-16f);
        i1 = 1.f / (wred_sum(ex1) + 1e-16f);
        i2 = 1.f / (wred_sum(ex2) + 1e-16f);
        i3 = 1.f / (wred_sum(ex3) + 1e-16f);
        if (act) {
            s_src[wslot][lane] = s;
            s_alpha[wslot][lane][0] = ex0;
            s_alpha[wslot][lane][1] = ex1;
            s_alpha[wslot][lane][2] = ex2;
            s_alpha[wslot][lane][3] = ex3;
        }
        __syncwarp();
        for (int j = 0; j < cnt; j++) {
            int sj = s_src[wslot][j];
            float a = s_alpha[wslot][j][hsel];
            float4 hv = ((const float4*)(g_h1 + (size_t)sj * 128))[lane];
            acc.x = fmaf(hv.x, a, acc.x);
            acc.y = fmaf(hv.y, a, acc.y);
            acc.z = fmaf(hv.z, a, acc.z);
            acc.w = fmaf(hv.w, a, acc.w);
        }
    } else {
        // -------- generic: max pass + fused sum/accumulate pass --------
        float m0 = -1e30f, m1 = -1e30f, m2 = -1e30f, m3 = -1e30f;
        for (int i = beg + lane; i < end; i += 32) {
            int s = g_csrc[i];
            float4 as = ((const float4*)g_al1s)[s];
            m0 = fmaxf(m0, lrelu(as.x + ad.x));
            m1 = fmaxf(m1, lrelu(as.y + ad.y));
            m2 = fmaxf(m2, lrelu(as.z + ad.z));
            m3 = fmaxf(m3, lrelu(as.w + ad.w));
        }
        m0 = wred_max(m0); m1 = wred_max(m1); m2 = wred_max(m2); m3 = wred_max(m3);
        float s0 = 0.f, s1 = 0.f, s2 = 0.f, s3 = 0.f;
        for (int base = beg; base < end; base += 32) {
            int c = min(32, end - base);
            int i = base + lane;
            if (i < end) {
                int s = g_csrc[i];
                s_src[wslot][lane] = s;
                float4 as = ((const float4*)g_al1s)[s];
                float ex0 = __expf(lrelu(as.x + ad.x) - m0);
                float ex1 = __expf(lrelu(as.y + ad.y) - m1);
                float ex2 = __expf(lrelu(as.z + ad.z) - m2);
                float ex3 = __expf(lrelu(as.w + ad.w) - m3);
                s0 += ex0; s1 += ex1; s2 += ex2; s3 += ex3;
                s_alpha[wslot][lane][0] = ex0;
                s_alpha[wslot][lane][1] = ex1;
                s_alpha[wslot][lane][2] = ex2;
                s_alpha[wslot][lane][3] = ex3;
            }
            __syncwarp();
            for (int j = 0; j < c; j++) {
                int sj = s_src[wslot][j];
                float a = s_alpha[wslot][j][hsel];
                float4 hv = ((const float4*)(g_h1 + (size_t)sj * 128))[lane];
                acc.x = fmaf(hv.x, a, acc.x);
                acc.y = fmaf(hv.y, a, acc.y);
                acc.z = fmaf(hv.z, a, acc.z);
                acc.w = fmaf(hv.w, a, acc.w);
            }
            __syncwarp();
        }
        i0 = 1.f / (wred_sum(s0) + 1e-16f);
        i1 = 1.f / (wred_sum(s1) + 1e-16f);
        i2 = 1.f / (wred_sum(s2) + 1e-16f);
        i3 = 1.f / (wred_sum(s3) + 1e-16f);
    }
    float inv = (hsel == 0) ? i0 : (hsel == 1) ? i1 : (hsel == 2) ? i2 : i3;
    acc.x *= inv; acc.y *= inv; acc.z *= inv; acc.w *= inv;
    ((float4*)(g_agg1 + (size_t)d * 128))[lane] = acc;
}

// ---------------- aggregation layer 2 (H=4, 16 ch/head, C=64) ----------------
__global__ void k_agg2(int N) {
    __shared__ float s_alpha[8][32][4];
    __shared__ int   s_src[8][32];
    int wslot = threadIdx.x >> 5;
    int lane = threadIdx.x & 31;
    int d = blockIdx.x * 8 + wslot;
    if (d >= N) return;
    int beg = g_rowptr[d], end = g_rowptr[d + 1];
    int cnt = end - beg;
    float4 ad = ((const float4*)g_al2d)[d];
    float2 acc = make_float2(0.f, 0.f);
    int hsel = lane >> 3;  // 2 contiguous channels per lane
    float i0, i1, i2, i3;

    if (cnt <= 32) {
        bool act = lane < cnt;
        int s = act ? g_csrc[beg + lane] : 0;
        float4 as = act ? ((const float4*)g_al2s)[s] : make_float4(0.f, 0.f, 0.f, 0.f);
        float e0 = act ? lrelu(as.x + ad.x) : -1e30f;
        float e1 = act ? lrelu(as.y + ad.y) : -1e30f;
        float e2 = act ? lrelu(as.z + ad.z) : -1e30f;
        float e3 = act ? lrelu(as.w + ad.w) : -1e30f;
        float m0 = wred_max(e0), m1 = wred_max(e1), m2 = wred_max(e2), m3 = wred_max(e3);
        float ex0 = act ? __expf(e0 - m0) : 0.f;
        float ex1 = act ? __expf(e1 - m1) : 0.f;
        float ex2 = act ? __expf(e2 - m2) : 0.f;
        float ex3 = act ? __expf(e3 - m3) : 0.f;
        i0 = 1.f / (wred_sum(ex0) + 1e-16f);
        i1 = 1.f / (wred_sum(ex1) + 1e-16f);
        i2 = 1.f / (wred_sum(ex2) + 1e-16f);
        i3 = 1.f / (wred_sum(ex3) + 1e-16f);
        if (act) {
            s_src[wslot][lane] = s;
            s_alpha[wslot][lane][0] = ex0;
            s_alpha[wslot][lane][1] = ex1;
            s_alpha[wslot][lane][2] = ex2;
            s_alpha[wslot][lane][3] = ex3;
        }
        __syncwarp();
        for (int j = 0; j < cnt; j++) {
            int sj = s_src[wslot][j];
            float a = s_alpha[wslot][j][hsel];
            float2 hv = ((const float2*)(g_h2 + (size_t)sj * 64))[lane];
            acc.x = fmaf(hv.x, a, acc.x);
            acc.y = fmaf(hv.y, a, acc.y);
        }
    } else {
        float m0 = -1e30f, m1 = -1e30f, m2 = -1e30f, m3 = -1e30f;
        for (int i = beg + lane; i < end; i += 32) {
            int s = g_csrc[i];
            float4 as = ((const float4*)g_al2s)[s];
            m0 = fmaxf(m0, lrelu(as.x + ad.x));
            m1 = fmaxf(m1, lrelu(as.y + ad.y));
            m2 = fmaxf(m2, lrelu(as.z + ad.z));
            m3 = fmaxf(m3, lrelu(as.w + ad.w));
        }
        m0 = wred_max(m0); m1 = wred_max(m1); m2 = wred_max(m2); m3 = wred_max(m3);
        float s0 = 0.f, s1 = 0.f, s2 = 0.f, s3 = 0.f;
        for (int base = beg; base < end; base += 32) {
            int c = min(32, end - base);
            int i = base + lane;
            if (i < end) {
                int s = g_csrc[i];
                s_src[wslot][lane] = s;
                float4 as = ((const float4*)g_al2s)[s];
                float ex0 = __expf(lrelu(as.x + ad.x) - m0);
                float ex1 = __expf(lrelu(as.y + ad.y) - m1);
                float ex2 = __expf(lrelu(as.z + ad.z) - m2);
                float ex3 = __expf(lrelu(as.w + ad.w) - m3);
                s0 += ex0; s1 += ex1; s2 += ex2; s3 += ex3;
                s_alpha[wslot][lane][0] = ex0;
                s_alpha[wslot][lane][1] = ex1;
                s_alpha[wslot][lane][2] = ex2;
                s_alpha[wslot][lane][3] = ex3;
            }
            __syncwarp();
            for (int j = 0; j < c; j++) {
                int sj = s_src[wslot][j];
                float a = s_alpha[wslot][j][hsel];
                float2 hv = ((const float2*)(g_h2 + (size_t)sj * 64))[lane];
                acc.x = fmaf(hv.x, a, acc.x);
                acc.y = fmaf(hv.y, a, acc.y);
            }
            __syncwarp();
        }
        i0 = 1.f / (wred_sum(s0) + 1e-16f);
        i1 = 1.f / (wred_sum(s1) + 1e-16f);
        i2 = 1.f / (wred_sum(s2) + 1e-16f);
        i3 = 1.f / (wred_sum(s3) + 1e-16f);
    }
    float inv = (hsel == 0) ? i0 : (hsel == 1) ? i1 : (hsel == 2) ? i2 : i3;
    acc.x *= inv; acc.y *= inv;
    ((float2*)(g_agg2 + (size_t)d * 64))[lane] = acc;
}

// ---------------- layer 3 aggregation + sigmoid output ----------------
__global__ void k_agg3(const float* __restrict__ as3, const float* __restrict__ ad3,
                       const float* __restrict__ b3, float* __restrict__ out, int N) {
    int gw = (blockIdx.x * blockDim.x + threadIdx.x) >> 5;
    int lane = threadIdx.x & 31;
    if (gw >= N) return;
    float a_s = as3[0], a_d = ad3[0];
    float hd = g_h3[gw] * a_d;
    int beg = g_rowptr[gw], end = g_rowptr[gw + 1];
    int cnt = end - beg;
    float se, sv;
    if (cnt <= 32) {
        bool act = lane < cnt;
        float hs = act ? g_h3[g_csrc[beg + lane]] : 0.f;
        float e = act ? lrelu(hs * a_s + hd) : -1e30f;
        float m = wred_max(e);
        float ex = act ? __expf(e - m) : 0.f;
        se = wred_sum(ex);
        sv = wred_sum(ex * hs);
    } else {
        float m = -1e30f;
        for (int i = beg + lane; i < end; i += 32) {
            float e = lrelu(g_h3[g_csrc[i]] * a_s + hd);
            m = fmaxf(m, e);
        }
        m = wred_max(m);
        se = 0.f; sv = 0.f;
        for (int i = beg + lane; i < end; i += 32) {
            float hs = g_h3[g_csrc[i]];
            float ex = __expf(lrelu(hs * a_s + hd) - m);
            se += ex;
            sv = fmaf(ex, hs, sv);
        }
        se = wred_sum(se);
        sv = wred_sum(sv);
    }
    if (lane == 0) {
        float o = sv / (se + 1e-16f) + b3[0];
        out[gw] = 100.f / (1.f + expf(-o));
    }
}

// ---------------- launch ----------------
extern "C" void kernel_launch(void* const* d_in, const int* in_sizes, int n_in,
                              void* d_out, int out_size) {
    const float* x   = (const float*)d_in[0];
    const int*   ei  = (const int*)d_in[1];   // int32 or int64 (auto-detected)
    const float* W1  = (const float*)d_in[2];
    const float* as1 = (const float*)d_in[3];
    const float* ad1 = (const float*)d_in[4];
    const float* b1  = (const float*)d_in[5];
    const float* W2  = (const float*)d_in[6];
    const float* as2 = (const float*)d_in[7];
    const float* ad2 = (const float*)d_in[8];
    const float* b2  = (const float*)d_in[9];
    const float* W3  = (const float*)d_in[10];
    const float* as3 = (const float*)d_in[11];
    const float* ad3 = (const float*)d_in[12];
    const float* b3  = (const float*)d_in[13];
    int N = in_sizes[0] / 7;
    int E = in_sizes[1] / 2;
    float* out = (float*)d_out;

    int ntile = (N + SCAN_TILE - 1) / SCAN_TILE;

    k_detect<<<1, 32>>>(ei);
    k_zero<<<(N + 255) / 256, 256>>>(N);
    k_count<<<(E + 255) / 256, 256>>>(ei, E);
    k_bsum<<<ntile, SCAN_BLK>>>(N);
    k_bscan<<<1, 32>>>(N);
    k_wptr<<<ntile, SCAN_BLK>>>(N);
    k_scatter<<<(E + 255) / 256, 256>>>(ei, E);
    k_self<<<(N + 255) / 256, 256>>>(N);

    k_l1<<<(N * 32 + 255) / 256, 256>>>(x, W1, as1, ad1, N);
    k_agg1<<<(N + 7) / 8, 256>>>(N);
    k_l2<<<2048, 128>>>(W2, b1, as2, ad2, N);
    k_agg2<<<(N + 7) / 8, 256>>>(N);
    k_l3<<<(N * 32 + 255) / 256, 256>>>(W3, b2, N);
    k_agg3<<<(N + 7) / 8, 256>>>(as3, ad3, b3, out, N);
}